// round 9
// baseline (speedup 1.0000x reference)
#include <cuda_runtime.h>
#include <cuda_bf16.h>
#include <math.h>

// Problem constants
#define B  64
#define S  64
#define H  512
#define E  256
#define V  32000
#define T  32
#define EPS 1e-5f
#define NBLK 128   // persistent decode-loop blocks (all resident: 128 < 148 SMs)

// ---------------- scratch (device globals; no allocation allowed) ----------------
__device__ float g_enc[B * S * H];        // LN(encoder_hidden)          8 MB
__device__ float g_pk [B * S * H];        // projected keys              8 MB
__device__ float g_x  [T * B * E];        // LN(emb[targets]) [T,B,E]    2 MB
__device__ float g_gx [T * B * 4 * H];    // x_t @ w_ih_x^T   [T*B,2048] 16 MB
__device__ float g_h  [B * H];
__device__ float g_c  [B * H];
__device__ float g_ctx[B * H];
__device__ float g_gpart[4][B * 4 * H];   // split-K partials for gates
__device__ float g_hs [B * T * H];        // all hidden states           4 MB
__device__ __nv_bfloat16 g_whi[V * H];    // out_w hi (bf16)             32.8 MB
__device__ __nv_bfloat16 g_wlo[V * H];    // out_w lo (bf16)             32.8 MB
__device__ unsigned g_barcnt;             // software grid barrier counter

// ---------------- init h0, c0 ----------------
__global__ void init_hc_kernel(const float* __restrict__ hn, const float* __restrict__ cn,
                               const float* __restrict__ phw, const float* __restrict__ phb,
                               const float* __restrict__ pcw, const float* __restrict__ pcb) {
    int b = blockIdx.x, u = threadIdx.x;   // block 512
    float h = phb[0], c = pcb[0];
#pragma unroll
    for (int l = 0; l < 4; l++) {
        h = fmaf(hn[(l * B + b) * H + u], phw[l], h);
        c = fmaf(cn[(l * B + b) * H + u], pcw[l], c);
    }
    g_h[b * H + u] = h;
    g_c[b * H + u] = c;
}

// ---------------- LayerNorm width 512 (encoder) ----------------
__global__ void ln512_kernel(const float* __restrict__ x, const float* __restrict__ g,
                             const float* __restrict__ bta, float* __restrict__ out) {
    int r = blockIdx.x;              // 4096 rows
    int tid = threadIdx.x;           // 256 threads
    const float* row = x + r * 512;
    float v0 = row[tid], v1 = row[tid + 256];
    float s = v0 + v1, s2 = v0 * v0 + v1 * v1;
    __shared__ float rs[8], rs2[8];
#pragma unroll
    for (int o = 16; o > 0; o >>= 1) {
        s  += __shfl_xor_sync(0xffffffffu, s, o);
        s2 += __shfl_xor_sync(0xffffffffu, s2, o);
    }
    int lane = tid & 31, w = tid >> 5;
    if (lane == 0) { rs[w] = s; rs2[w] = s2; }
    __syncthreads();
    s = 0.f; s2 = 0.f;
#pragma unroll
    for (int i = 0; i < 8; i++) { s += rs[i]; s2 += rs2[i]; }
    float mean = s * (1.f / 512.f);
    float var  = s2 * (1.f / 512.f) - mean * mean;
    float inv  = rsqrtf(var + EPS);
    out[r * 512 + tid]       = (v0 - mean) * inv * g[tid]       + bta[tid];
    out[r * 512 + tid + 256] = (v1 - mean) * inv * g[tid + 256] + bta[tid + 256];
}

// ---------------- embed + LayerNorm width 256 -> g_x[t*B+b] ----------------
__global__ void emb_ln_kernel(const int* __restrict__ targets, const float* __restrict__ emb,
                              const float* __restrict__ g, const float* __restrict__ bta) {
    int r = blockIdx.x;              // 2048 rows = b*T+t
    int b = r >> 5, t = r & 31;
    int tid = threadIdx.x;           // 256
    int tok = targets[b * T + t];
    float v = emb[(long long)tok * 256 + tid];
    float s = v, s2 = v * v;
    __shared__ float rs[8], rs2[8];
#pragma unroll
    for (int o = 16; o > 0; o >>= 1) {
        s  += __shfl_xor_sync(0xffffffffu, s, o);
        s2 += __shfl_xor_sync(0xffffffffu, s2, o);
    }
    int lane = tid & 31, w = tid >> 5;
    if (lane == 0) { rs[w] = s; rs2[w] = s2; }
    __syncthreads();
    s = 0.f; s2 = 0.f;
#pragma unroll
    for (int i = 0; i < 8; i++) { s += rs[i]; s2 += rs2[i]; }
    float mean = s * (1.f / 256.f);
    float var  = s2 * (1.f / 256.f) - mean * mean;
    float inv  = rsqrtf(var + EPS);
    g_x[(t * B + b) * 256 + tid] = (v - mean) * inv * g[tid] + bta[tid];
}

// ---------------- generic 64x64-tile GEMM: C[m,n] = sum_k A[m,k]*W[n,k] (+bias) ----------------
__global__ void gemm64(const float* __restrict__ A, int lda,
                       const float* __restrict__ W, int ldw,
                       const float* __restrict__ bias,
                       float* __restrict__ C, int ldc, int K) {
    __shared__ float As[32][65];
    __shared__ float Ws[32][65];
    int tid = threadIdx.x;                 // 256
    int tx = tid & 15, ty = tid >> 4;
    int m0 = blockIdx.x * 64, n0 = blockIdx.y * 64;
    float acc[4][4] = {};
    for (int k0 = 0; k0 < K; k0 += 32) {
#pragma unroll
        for (int i = 0; i < 8; i++) {
            int li = tid + i * 256;
            int k = li & 31, m = li >> 5;
            As[k][m] = A[(m0 + m) * lda + k0 + k];
            Ws[k][m] = W[(n0 + m) * ldw + k0 + k];
        }
        __syncthreads();
#pragma unroll
        for (int k = 0; k < 32; k++) {
            float a[4], w[4];
#pragma unroll
            for (int i = 0; i < 4; i++) a[i] = As[k][ty * 4 + i];
#pragma unroll
            for (int j = 0; j < 4; j++) w[j] = Ws[k][tx * 4 + j];
#pragma unroll
            for (int i = 0; i < 4; i++)
#pragma unroll
                for (int j = 0; j < 4; j++)
                    acc[i][j] = fmaf(a[i], w[j], acc[i][j]);
        }
        __syncthreads();
    }
#pragma unroll
    for (int i = 0; i < 4; i++)
#pragma unroll
        for (int j = 0; j < 4; j++) {
            int m = m0 + ty * 4 + i, n = n0 + tx * 4 + j;
            float vv = acc[i][j];
            if (bias) vv += bias[n];
            C[m * ldc + n] = vv;
        }
}

// ================= persistent fused decode loop =================

__global__ void reset_bar_kernel() { g_barcnt = 0u; }

__device__ __forceinline__ void grid_bar(unsigned target) {
    __syncthreads();
    if (threadIdx.x == 0) {
        __threadfence();                     // release: push this block's writes
        atomicAdd(&g_barcnt, 1u);
        unsigned v;
        do {
            asm volatile("ld.acquire.gpu.u32 %0, [%1];"
                         : "=r"(v) : "l"(&g_barcnt) : "memory");
        } while (v < target);
        __threadfence();                     // acquire side: invalidate stale L1 lines
    }
    __syncthreads();
}

__device__ __forceinline__ void attn_phase(int b,
        const float* __restrict__ qw, const float* __restrict__ qb,
        const float* __restrict__ ew,
        float* sh, float* sq, float* se, float* sa) {
    int tid = threadIdx.x;               // 256
    int lane = tid & 31, warp = tid >> 5; // 8 warps

    for (int i = tid; i < 512; i += 256) sh[i] = g_h[b * 512 + i];
    __syncthreads();

    // q projection: warp per output row of q_w
    for (int gidx = warp; gidx < 512; gidx += 8) {
        const float* wr = qw + gidx * 512;
        float acc = 0.f;
#pragma unroll
        for (int i = 0; i < 16; i++) {
            int k = lane + i * 32;
            acc = fmaf(sh[k], wr[k], acc);
        }
#pragma unroll
        for (int o = 16; o > 0; o >>= 1) acc += __shfl_xor_sync(0xffffffffu, acc, o);
        if (lane == 0) sq[gidx] = acc + qb[gidx];
    }
    __syncthreads();

    // energies
    for (int s = warp; s < 64; s += 8) {
        const float* pk = g_pk + (b * 64 + s) * 512;
        float acc = 0.f;
#pragma unroll
        for (int i = 0; i < 16; i++) {
            int k = lane + i * 32;
            acc = fmaf(tanhf(sq[k] + pk[k]), ew[k], acc);
        }
#pragma unroll
        for (int o = 16; o > 0; o >>= 1) acc += __shfl_xor_sync(0xffffffffu, acc, o);
        if (lane == 0) se[s] = acc;
    }
    __syncthreads();

    // softmax over 64 (warp 0)
    if (warp == 0) {
        float e0 = se[lane], e1 = se[lane + 32];
        float mx = fmaxf(e0, e1);
#pragma unroll
        for (int o = 16; o > 0; o >>= 1) mx = fmaxf(mx, __shfl_xor_sync(0xffffffffu, mx, o));
        float x0 = expf(e0 - mx), x1 = expf(e1 - mx);
        float sm = x0 + x1;
#pragma unroll
        for (int o = 16; o > 0; o >>= 1) sm += __shfl_xor_sync(0xffffffffu, sm, o);
        float inv = 1.f / sm;
        sa[lane] = x0 * inv; sa[lane + 32] = x1 * inv;
    }
    __syncthreads();

    // context
    for (int hh = tid; hh < 512; hh += 256) {
        float acc = 0.f;
#pragma unroll 8
        for (int s = 0; s < 64; s++)
            acc = fmaf(sa[s], g_enc[(b * 64 + s) * 512 + hh], acc);
        g_ctx[b * 512 + hh] = acc;
    }
}

__device__ __forceinline__ void gates_phase(int bx,
        const float* __restrict__ wih, const float* __restrict__ whh,
        float (*As)[65], float (*Ws)[65]) {
    int p  = bx >> 5;                     // 0..3
    int n0 = (bx & 31) * 64;              // n-tile
    const float* A; const float* W; int ldw; int kbase;
    if (p < 2) { A = g_ctx; W = wih; ldw = 768; kbase = p * 256; }
    else       { A = g_h;   W = whh; ldw = 512; kbase = (p - 2) * 256; }
    int tid = threadIdx.x;
    int tx = tid & 15, ty = tid >> 4;
    float acc[4][4] = {};
    for (int kk = 0; kk < 256; kk += 32) {
#pragma unroll
        for (int i = 0; i < 8; i++) {
            int li = tid + i * 256;
            int k = li & 31, m = li >> 5;
            As[k][m] = A[m * 512 + kbase + kk + k];
            Ws[k][m] = W[(n0 + m) * ldw + kbase + kk + k];
        }
        __syncthreads();
#pragma unroll
        for (int k = 0; k < 32; k++) {
            float a[4], w[4];
#pragma unroll
            for (int i = 0; i < 4; i++) a[i] = As[k][ty * 4 + i];
#pragma unroll
            for (int j = 0; j < 4; j++) w[j] = Ws[k][tx * 4 + j];
#pragma unroll
            for (int i = 0; i < 4; i++)
#pragma unroll
                for (int j = 0; j < 4; j++)
                    acc[i][j] = fmaf(a[i], w[j], acc[i][j]);
        }
        __syncthreads();
    }
#pragma unroll
    for (int i = 0; i < 4; i++)
#pragma unroll
        for (int j = 0; j < 4; j++) {
            int m = ty * 4 + i, n = n0 + tx * 4 + j;
            g_gpart[p][m * 2048 + n] = acc[i][j];
        }
}

__device__ __forceinline__ void lstm_phase(int b, int t,
        const float* __restrict__ bih, const float* __restrict__ bhh) {
    int base = b * 2048;
    for (int u = threadIdx.x; u < 512; u += 256) {
        float gate[4];
#pragma unroll
        for (int gi = 0; gi < 4; gi++) {
            int n = gi * 512 + u;
            float vv = bih[n] + bhh[n] + g_gx[(t * B + b) * 2048 + n];
            vv += g_gpart[0][base + n] + g_gpart[1][base + n]
                + g_gpart[2][base + n] + g_gpart[3][base + n];
            gate[gi] = vv;
        }
        float i_s = 1.f / (1.f + expf(-gate[0]));
        float f_s = 1.f / (1.f + expf(-gate[1]));
        float g_t = tanhf(gate[2]);
        float o_s = 1.f / (1.f + expf(-gate[3]));
        float c2 = f_s * g_c[b * 512 + u] + i_s * g_t;
        float h2 = o_s * tanhf(c2);
        g_c[b * 512 + u] = c2;
        g_h[b * 512 + u] = h2;
        g_hs[(b * T + t) * 512 + u] = h2;
    }
}

__global__ __launch_bounds__(256) void decode_loop_kernel(
        const float* __restrict__ qw, const float* __restrict__ qb,
        const float* __restrict__ ew,
        const float* __restrict__ wih, const float* __restrict__ whh,
        const float* __restrict__ bih, const float* __restrict__ bhh) {
    __shared__ float sh[512], sq[512], se[64], sa[64];
    __shared__ float As[32][65], Ws[32][65];
    int bx = blockIdx.x;
    unsigned ep = 0;
    for (int t = 0; t < T; t++) {
        if (bx < 64) attn_phase(bx, qw, qb, ew, sh, sq, se, sa);
        ep++; grid_bar(ep * NBLK);
        gates_phase(bx, wih, whh, As, Ws);
        ep++; grid_bar(ep * NBLK);
        if (bx < 64) lstm_phase(bx, t, bih, bhh);
        ep++; grid_bar(ep * NBLK);
    }
}

// ---------------- split out_w into bf16 hi/lo ----------------
__global__ void convert_w_kernel(const float* __restrict__ w,
                                 __nv_bfloat16* __restrict__ whi,
                                 __nv_bfloat16* __restrict__ wlo) {
    int i = (blockIdx.x * 256 + threadIdx.x) * 4;
    float4 v = *reinterpret_cast<const float4*>(w + i);
    float vv[4] = {v.x, v.y, v.z, v.w};
    __nv_bfloat16 h[4], l[4];
#pragma unroll
    for (int j = 0; j < 4; j++) {
        h[j] = __float2bfloat16_rn(vv[j]);
        l[j] = __float2bfloat16_rn(vv[j] - __bfloat162float(h[j]));
    }
    *reinterpret_cast<uint2*>(whi + i) = *reinterpret_cast<uint2*>(h);
    *reinterpret_cast<uint2*>(wlo + i) = *reinterpret_cast<uint2*>(l);
}

// ---------------- tensor-core final projection (bf16 2-term split, 3 MMA passes) ----------------
// C[2048, 32000] = hs[2048,512] @ out_w[32000,512]^T + out_b
// Block tile 128x128, 8 warps (2M x 4N), SMEM tiles 128x64 bf16 with SW128 swizzle.

#define LDM_X4(R, addr) \
    asm volatile("ldmatrix.sync.aligned.m8n8.x4.shared.b16 {%0,%1,%2,%3}, [%4];" \
                 : "=r"((R)[0]), "=r"((R)[1]), "=r"((R)[2]), "=r"((R)[3]) : "r"(addr))

#define MMA16816(D, Aa, Bb) \
    asm volatile("mma.sync.aligned.m16n8k16.row.col.f32.bf16.bf16.f32 " \
                 "{%0,%1,%2,%3}, {%4,%5,%6,%7}, {%8,%9}, {%0,%1,%2,%3};" \
                 : "+f"((D)[0]), "+f"((D)[1]), "+f"((D)[2]), "+f"((D)[3]) \
                 : "r"((Aa)[0]), "r"((Aa)[1]), "r"((Aa)[2]), "r"((Aa)[3]), \
                   "r"((Bb)[0]), "r"((Bb)[1]))

__global__ __launch_bounds__(256) void gemm_bf16_split(
    const float* __restrict__ A,              // [2048][512] fp32
    const __nv_bfloat16* __restrict__ Whi,    // [V][512]
    const __nv_bfloat16* __restrict__ Wlo,    // [V][512]
    const float* __restrict__ bias,
    float* __restrict__ C)
{
    extern __shared__ unsigned char smem[];
    const unsigned oAhi = 0, oAlo = 16384, oWhi = 32768, oWlo = 49152;
    unsigned sbase = (unsigned)__cvta_generic_to_shared(smem);

    int tid = threadIdx.x;
    int m0 = blockIdx.x * 128;
    int n0 = blockIdx.y * 128;
    int warp = tid >> 5, lane = tid & 31;
    int wm = (warp & 1) * 64;        // warp M offset within tile
    int wn = (warp >> 1) * 32;       // warp N offset within tile

    float acc[4][4][4];
#pragma unroll
    for (int i = 0; i < 4; i++)
#pragma unroll
        for (int j = 0; j < 4; j++)
#pragma unroll
            for (int k = 0; k < 4; k++) acc[i][j][k] = 0.f;

    for (int k0 = 0; k0 < 512; k0 += 64) {
        // ---- load W hi/lo tiles (bf16, 16B vectors, swizzled) ----
#pragma unroll
        for (int i = 0; i < 4; i++) {
            int id = tid + i * 256;            // 0..1023  (128 rows x 8 chunks)
            int r = id >> 3, c = id & 7;
            unsigned dst = (unsigned)(r * 128 + ((c ^ (r & 7)) << 4));
            const uint4* shi = reinterpret_cast<const uint4*>(Whi + (size_t)(n0 + r) * 512 + k0 + c * 8);
            const uint4* slo = reinterpret_cast<const uint4*>(Wlo + (size_t)(n0 + r) * 512 + k0 + c * 8);
            *reinterpret_cast<uint4*>(smem + oWhi + dst) = *shi;
            *reinterpret_cast<uint4*>(smem + oWlo + dst) = *slo;
        }
        // ---- load + split A tile (fp32 -> bf16 hi/lo) ----
#pragma unroll
        for (int i = 0; i < 4; i++) {
            int id = tid + i * 256;
            int r = id >> 3, c = id & 7;
            const float4* src = reinterpret_cast<const float4*>(A + (size_t)(m0 + r) * 512 + k0 + c * 8);
            float4 v0 = src[0], v1 = src[1];
            float vv[8] = {v0.x, v0.y, v0.z, v0.w, v1.x, v1.y, v1.z, v1.w};
            __nv_bfloat16 h[8], l[8];
#pragma unroll
            for (int j = 0; j < 8; j++) {
                h[j] = __float2bfloat16_rn(vv[j]);
                l[j] = __float2bfloat16_rn(vv[j] - __bfloat162float(h[j]));
            }
            unsigned dst = (unsigned)(r * 128 + ((c ^ (r & 7)) << 4));
            *reinterpret_cast<uint4*>(smem + oAhi + dst) = *reinterpret_cast<uint4*>(h);
            *reinterpret_cast<uint4*>(smem + oAlo + dst) = *reinterpret_cast<uint4*>(l);
        }
        __syncthreads();

        // ---- compute: 4 k16 steps per chunk ----
#pragma unroll
        for (int kk = 0; kk < 64; kk += 16) {
            unsigned a_hi[4][4], a_lo[4][4];
#pragma unroll
            for (int ma = 0; ma < 4; ma++) {
                int r = wm + ma * 16 + (lane & 15);
                int c = (kk >> 3) + (lane >> 4);
                unsigned off = (unsigned)(r * 128 + ((c ^ (r & 7)) << 4));
                LDM_X4(a_hi[ma], sbase + oAhi + off);
                LDM_X4(a_lo[ma], sbase + oAlo + off);
            }
#pragma unroll
            for (int nb = 0; nb < 2; nb++) {
                int g  = lane >> 3;
                int rn = wn + nb * 16 + ((g >> 1) << 3) + (lane & 7);
                int c  = (kk >> 3) + (g & 1);
                unsigned off = (unsigned)(rn * 128 + ((c ^ (rn & 7)) << 4));
                unsigned b_hi[4], b_lo[4];
                LDM_X4(b_hi, sbase + oWhi + off);
                LDM_X4(b_lo, sbase + oWlo + off);
#pragma unroll
                for (int ma = 0; ma < 4; ma++) {
#pragma unroll
                    for (int s = 0; s < 2; s++) {
                        int na = nb * 2 + s;
                        MMA16816(acc[ma][na], a_hi[ma], b_hi + s * 2);
                        MMA16816(acc[ma][na], a_hi[ma], b_lo + s * 2);
                        MMA16816(acc[ma][na], a_lo[ma], b_hi + s * 2);
                    }
                }
            }
        }
        __syncthreads();
    }

    // ---- epilogue: add bias, store fp32 ----
#pragma unroll
    for (int ma = 0; ma < 4; ma++) {
        int mrow = m0 + wm + ma * 16 + (lane >> 2);
#pragma unroll
        for (int na = 0; na < 4; na++) {
            int nc = n0 + wn + na * 8 + (lane & 3) * 2;
            float b0 = bias[nc], b1 = bias[nc + 1];
            float2 v0 = {acc[ma][na][0] + b0, acc[ma][na][1] + b1};
            float2 v1 = {acc[ma][na][2] + b0, acc[ma][na][3] + b1};
            *reinterpret_cast<float2*>(C + (size_t)mrow * V + nc)       = v0;
            *reinterpret_cast<float2*>(C + (size_t)(mrow + 8) * V + nc) = v1;
        }
    }
}

// ---------------- launcher ----------------
extern "C" void kernel_launch(void* const* d_in, const int* in_sizes, int n_in,
                              void* d_out, int out_size) {
    const int*   targets = (const int*)  d_in[0];
    const float* ench    = (const float*)d_in[1];
    const float* hn      = (const float*)d_in[2];
    const float* cn      = (const float*)d_in[3];
    int off = (in_sizes[4] == 1) ? 5 : 4;
    const float* emb  = (const float*)d_in[off + 0];
    const float* lng  = (const float*)d_in[off + 1];
    const float* lnb  = (const float*)d_in[off + 2];
    const float* leg  = (const float*)d_in[off + 3];
    const float* leb  = (const float*)d_in[off + 4];
    const float* phw  = (const float*)d_in[off + 5];
    const float* phb  = (const float*)d_in[off + 6];
    const float* pcw  = (const float*)d_in[off + 7];
    const float* pcb  = (const float*)d_in[off + 8];
    const float* qw   = (const float*)d_in[off + 9];
    const float* qb   = (const float*)d_in[off + 10];
    const float* kw   = (const float*)d_in[off + 11];
    const float* ew   = (const float*)d_in[off + 12];
    const float* wih  = (const float*)d_in[off + 13];
    const float* whh  = (const float*)d_in[off + 14];
    const float* bih  = (const float*)d_in[off + 15];
    const float* bhh  = (const float*)d_in[off + 16];
    const float* outw = (const float*)d_in[off + 17];
    const float* outb = (const float*)d_in[off + 18];

    float *p_enc, *p_pk, *p_x, *p_gx, *p_hs;
    __nv_bfloat16 *p_whi, *p_wlo;
    cudaGetSymbolAddress((void**)&p_enc, g_enc);
    cudaGetSymbolAddress((void**)&p_pk,  g_pk);
    cudaGetSymbolAddress((void**)&p_x,   g_x);
    cudaGetSymbolAddress((void**)&p_gx,  g_gx);
    cudaGetSymbolAddress((void**)&p_hs,  g_hs);
    cudaGetSymbolAddress((void**)&p_whi, g_whi);
    cudaGetSymbolAddress((void**)&p_wlo, g_wlo);

    cudaFuncSetAttribute(gemm_bf16_split,
                         cudaFuncAttributeMaxDynamicSharedMemorySize, 65536);

    // prologue (convert_w is independent; done up front)
    convert_w_kernel<<<(V * H) / 1024, 256>>>(outw, p_whi, p_wlo);
    init_hc_kernel<<<B, 512>>>(hn, cn, phw, phb, pcw, pcb);
    ln512_kernel<<<B * S, 256>>>(ench, lng, lnb, p_enc);
    emb_ln_kernel<<<B * T, 256>>>(targets, emb, leg, leb);
    // pk = enc @ k_w^T   [4096,512] x [512,512]
    gemm64<<<dim3(64, 8), 256>>>(p_enc, 512, kw, 512, nullptr, p_pk, 512, 512);
    // gx = x_all @ w_ih[:,512:768]^T  [2048,256]
    gemm64<<<dim3(32, 32), 256>>>(p_x, 256, wih + 512, 768, nullptr, p_gx, 2048, 256);

    // fused persistent decode loop (software grid barrier; counter reset each replay)
    reset_bar_kernel<<<1, 1>>>();
    decode_loop_kernel<<<NBLK, 256>>>(qw, qb, ew, wih, whh, bih, bhh);

    // final projection on tensor cores: preds = hs @ out_w^T + out_b
    gemm_bf16_split<<<dim3(16, 250), 256, 65536>>>(p_hs, p_whi, p_wlo, outb, (float*)d_out);
}

// round 13
// speedup vs baseline: 1.2665x; 1.2665x over previous
#include <cuda_runtime.h>
#include <cuda_bf16.h>
#include <math.h>

// Problem constants
#define B  64
#define S  64
#define H  512
#define E  256
#define V  32000
#define T  32
#define EPS 1e-5f

// ---------------- scratch (device globals; no allocation allowed) ----------------
__device__ float g_enc[B * S * H];        // LN(encoder_hidden)          8 MB
__device__ float g_pk [B * S * H];        // projected keys              8 MB
__device__ float g_x  [T * B * E];        // LN(emb[targets]) [T,B,E]    2 MB
__device__ float g_gx [T * B * 4 * H];    // x_t @ w_ih_x^T   [T*B,2048] 16 MB
__device__ float g_h  [B * H];
__device__ float g_c  [B * H];
__device__ float g_ctx[B * H];
__device__ float g_gpart[4][B * 4 * H];   // split-K partials for gates
__device__ float g_hs [B * T * H];        // all hidden states           4 MB
__device__ __nv_bfloat16 g_whi[V * H];    // out_w hi (bf16)             32.8 MB
__device__ __nv_bfloat16 g_wlo[V * H];    // out_w lo (bf16)             32.8 MB
__device__ __nv_bfloat16 g_ahi[B * T * H];// hs hi (bf16)                2 MB
__device__ __nv_bfloat16 g_alo[B * T * H];// hs lo (bf16)                2 MB

// ---------------- init h0, c0 ----------------
__global__ void init_hc_kernel(const float* __restrict__ hn, const float* __restrict__ cn,
                               const float* __restrict__ phw, const float* __restrict__ phb,
                               const float* __restrict__ pcw, const float* __restrict__ pcb) {
    int b = blockIdx.x, u = threadIdx.x;   // block 512
    float h = phb[0], c = pcb[0];
#pragma unroll
    for (int l = 0; l < 4; l++) {
        h = fmaf(hn[(l * B + b) * H + u], phw[l], h);
        c = fmaf(cn[(l * B + b) * H + u], pcw[l], c);
    }
    g_h[b * H + u] = h;
    g_c[b * H + u] = c;
}

// ---------------- LayerNorm width 512 (encoder) ----------------
__global__ void ln512_kernel(const float* __restrict__ x, const float* __restrict__ g,
                             const float* __restrict__ bta, float* __restrict__ out) {
    int r = blockIdx.x;              // 4096 rows
    int tid = threadIdx.x;           // 256 threads
    const float* row = x + r * 512;
    float v0 = row[tid], v1 = row[tid + 256];
    float s = v0 + v1, s2 = v0 * v0 + v1 * v1;
    __shared__ float rs[8], rs2[8];
#pragma unroll
    for (int o = 16; o > 0; o >>= 1) {
        s  += __shfl_xor_sync(0xffffffffu, s, o);
        s2 += __shfl_xor_sync(0xffffffffu, s2, o);
    }
    int lane = tid & 31, w = tid >> 5;
    if (lane == 0) { rs[w] = s; rs2[w] = s2; }
    __syncthreads();
    s = 0.f; s2 = 0.f;
#pragma unroll
    for (int i = 0; i < 8; i++) { s += rs[i]; s2 += rs2[i]; }
    float mean = s * (1.f / 512.f);
    float var  = s2 * (1.f / 512.f) - mean * mean;
    float inv  = rsqrtf(var + EPS);
    out[r * 512 + tid]       = (v0 - mean) * inv * g[tid]       + bta[tid];
    out[r * 512 + tid + 256] = (v1 - mean) * inv * g[tid + 256] + bta[tid + 256];
}

// ---------------- embed + LayerNorm width 256 -> g_x[t*B+b] ----------------
__global__ void emb_ln_kernel(const int* __restrict__ targets, const float* __restrict__ emb,
                              const float* __restrict__ g, const float* __restrict__ bta) {
    int r = blockIdx.x;              // 2048 rows = b*T+t
    int b = r >> 5, t = r & 31;
    int tid = threadIdx.x;           // 256
    int tok = targets[b * T + t];
    float v = emb[(long long)tok * 256 + tid];
    float s = v, s2 = v * v;
    __shared__ float rs[8], rs2[8];
#pragma unroll
    for (int o = 16; o > 0; o >>= 1) {
        s  += __shfl_xor_sync(0xffffffffu, s, o);
        s2 += __shfl_xor_sync(0xffffffffu, s2, o);
    }
    int lane = tid & 31, w = tid >> 5;
    if (lane == 0) { rs[w] = s; rs2[w] = s2; }
    __syncthreads();
    s = 0.f; s2 = 0.f;
#pragma unroll
    for (int i = 0; i < 8; i++) { s += rs[i]; s2 += rs2[i]; }
    float mean = s * (1.f / 256.f);
    float var  = s2 * (1.f / 256.f) - mean * mean;
    float inv  = rsqrtf(var + EPS);
    g_x[(t * B + b) * 256 + tid] = (v - mean) * inv * g[tid] + bta[tid];
}

// ---------------- generic 64x64-tile GEMM: C[m,n] = sum_k A[m,k]*W[n,k] (+bias) ----------------
__global__ void gemm64(const float* __restrict__ A, int lda,
                       const float* __restrict__ W, int ldw,
                       const float* __restrict__ bias,
                       float* __restrict__ C, int ldc, int K) {
    __shared__ float As[32][65];
    __shared__ float Ws[32][65];
    int tid = threadIdx.x;                 // 256
    int tx = tid & 15, ty = tid >> 4;
    int m0 = blockIdx.x * 64, n0 = blockIdx.y * 64;
    float acc[4][4] = {};
    for (int k0 = 0; k0 < K; k0 += 32) {
#pragma unroll
        for (int i = 0; i < 8; i++) {
            int li = tid + i * 256;
            int k = li & 31, m = li >> 5;
            As[k][m] = A[(m0 + m) * lda + k0 + k];
            Ws[k][m] = W[(n0 + m) * ldw + k0 + k];
        }
        __syncthreads();
#pragma unroll
        for (int k = 0; k < 32; k++) {
            float a[4], w[4];
#pragma unroll
            for (int i = 0; i < 4; i++) a[i] = As[k][ty * 4 + i];
#pragma unroll
            for (int j = 0; j < 4; j++) w[j] = Ws[k][tx * 4 + j];
#pragma unroll
            for (int i = 0; i < 4; i++)
#pragma unroll
                for (int j = 0; j < 4; j++)
                    acc[i][j] = fmaf(a[i], w[j], acc[i][j]);
        }
        __syncthreads();
    }
#pragma unroll
    for (int i = 0; i < 4; i++)
#pragma unroll
        for (int j = 0; j < 4; j++) {
            int m = m0 + ty * 4 + i, n = n0 + tx * 4 + j;
            float vv = acc[i][j];
            if (bias) vv += bias[n];
            C[m * ldc + n] = vv;
        }
}

// ---------------- attention step ----------------
__global__ void attn_kernel(const float* __restrict__ qw, const float* __restrict__ qb,
                            const float* __restrict__ ew) {
    int b = blockIdx.x;
    int tid = threadIdx.x;               // 256
    int lane = tid & 31, warp = tid >> 5; // 8 warps
    __shared__ float sh[512];
    __shared__ float sq[512];
    __shared__ float se[64];
    __shared__ float sa[64];

    for (int i = tid; i < 512; i += 256) sh[i] = g_h[b * 512 + i];
    __syncthreads();

    for (int gidx = warp; gidx < 512; gidx += 8) {
        const float* wr = qw + gidx * 512;
        float acc = 0.f;
#pragma unroll
        for (int i = 0; i < 16; i++) {
            int k = lane + i * 32;
            acc = fmaf(sh[k], wr[k], acc);
        }
#pragma unroll
        for (int o = 16; o > 0; o >>= 1) acc += __shfl_xor_sync(0xffffffffu, acc, o);
        if (lane == 0) sq[gidx] = acc + qb[gidx];
    }
    __syncthreads();

    for (int s = warp; s < 64; s += 8) {
        const float* pk = g_pk + (b * 64 + s) * 512;
        float acc = 0.f;
#pragma unroll
        for (int i = 0; i < 16; i++) {
            int k = lane + i * 32;
            acc = fmaf(tanhf(sq[k] + pk[k]), ew[k], acc);
        }
#pragma unroll
        for (int o = 16; o > 0; o >>= 1) acc += __shfl_xor_sync(0xffffffffu, acc, o);
        if (lane == 0) se[s] = acc;
    }
    __syncthreads();

    if (warp == 0) {
        float e0 = se[lane], e1 = se[lane + 32];
        float mx = fmaxf(e0, e1);
#pragma unroll
        for (int o = 16; o > 0; o >>= 1) mx = fmaxf(mx, __shfl_xor_sync(0xffffffffu, mx, o));
        float x0 = expf(e0 - mx), x1 = expf(e1 - mx);
        float sm = x0 + x1;
#pragma unroll
        for (int o = 16; o > 0; o >>= 1) sm += __shfl_xor_sync(0xffffffffu, sm, o);
        float inv = 1.f / sm;
        sa[lane] = x0 * inv; sa[lane + 32] = x1 * inv;
    }
    __syncthreads();

    for (int hh = tid; hh < 512; hh += 256) {
        float acc = 0.f;
#pragma unroll 8
        for (int s = 0; s < 64; s++)
            acc = fmaf(sa[s], g_enc[(b * 64 + s) * 512 + hh], acc);
        g_ctx[b * 512 + hh] = acc;
    }
}

// ---------------- gates split-K partial GEMM (M=64, N=2048, 4 K-chunks of 256) ----------------
__global__ void gates_part_kernel(const float* __restrict__ wih, const float* __restrict__ whh) {
    int p = blockIdx.y;                   // 0..3
    const float* A; const float* W; int ldw; int kbase;
    if (p < 2) { A = g_ctx; W = wih; ldw = 768; kbase = p * 256; }
    else       { A = g_h;   W = whh; ldw = 512; kbase = (p - 2) * 256; }
    int n0 = blockIdx.x * 64;
    __shared__ float As[32][65];
    __shared__ float Ws[32][65];
    int tid = threadIdx.x;
    int tx = tid & 15, ty = tid >> 4;
    float acc[4][4] = {};
    for (int kk = 0; kk < 256; kk += 32) {
#pragma unroll
        for (int i = 0; i < 8; i++) {
            int li = tid + i * 256;
            int k = li & 31, m = li >> 5;
            As[k][m] = A[m * 512 + kbase + kk + k];
            Ws[k][m] = W[(n0 + m) * ldw + kbase + kk + k];
        }
        __syncthreads();
#pragma unroll
        for (int k = 0; k < 32; k++) {
            float a[4], w[4];
#pragma unroll
            for (int i = 0; i < 4; i++) a[i] = As[k][ty * 4 + i];
#pragma unroll
            for (int j = 0; j < 4; j++) w[j] = Ws[k][tx * 4 + j];
#pragma unroll
            for (int i = 0; i < 4; i++)
#pragma unroll
                for (int j = 0; j < 4; j++)
                    acc[i][j] = fmaf(a[i], w[j], acc[i][j]);
        }
        __syncthreads();
    }
#pragma unroll
    for (int i = 0; i < 4; i++)
#pragma unroll
        for (int j = 0; j < 4; j++) {
            int m = ty * 4 + i, n = n0 + tx * 4 + j;
            g_gpart[p][m * 2048 + n] = acc[i][j];
        }
}

// ---------------- LSTM pointwise ----------------
__global__ void lstm_kernel(const float* __restrict__ bih, const float* __restrict__ bhh, int t) {
    int b = blockIdx.x, u = threadIdx.x;   // block 512
    int base = b * 2048;
    float gate[4];
#pragma unroll
    for (int gi = 0; gi < 4; gi++) {
        int n = gi * 512 + u;
        float vv = bih[n] + bhh[n] + g_gx[(t * B + b) * 2048 + n];
        vv += g_gpart[0][base + n] + g_gpart[1][base + n]
            + g_gpart[2][base + n] + g_gpart[3][base + n];
        gate[gi] = vv;
    }
    float i_s = 1.f / (1.f + expf(-gate[0]));
    float f_s = 1.f / (1.f + expf(-gate[1]));
    float g_t = tanhf(gate[2]);
    float o_s = 1.f / (1.f + expf(-gate[3]));
    float c2 = f_s * g_c[b * 512 + u] + i_s * g_t;
    float h2 = o_s * tanhf(c2);
    g_c[b * 512 + u] = c2;
    g_h[b * 512 + u] = h2;
    g_hs[(b * T + t) * 512 + u] = h2;
}

// ---------------- split fp32 -> bf16 hi/lo (generic) ----------------
__global__ void split_bf16_kernel(const float* __restrict__ w,
                                  __nv_bfloat16* __restrict__ whi,
                                  __nv_bfloat16* __restrict__ wlo) {
    int i = (blockIdx.x * 256 + threadIdx.x) * 4;
    float4 v = *reinterpret_cast<const float4*>(w + i);
    float vv[4] = {v.x, v.y, v.z, v.w};
    __nv_bfloat16 h[4], l[4];
#pragma unroll
    for (int j = 0; j < 4; j++) {
        h[j] = __float2bfloat16_rn(vv[j]);
        l[j] = __float2bfloat16_rn(vv[j] - __bfloat162float(h[j]));
    }
    *reinterpret_cast<uint2*>(whi + i) = *reinterpret_cast<uint2*>(h);
    *reinterpret_cast<uint2*>(wlo + i) = *reinterpret_cast<uint2*>(l);
}

// ---------------- tensor-core final projection (bf16 2-term split, pre-split operands) ----------------
// C[2048, 32000] = hs @ out_w^T + out_b, via 3 bf16 MMA passes (hi*hi + hi*lo + lo*hi).
// Identical structure/instruction mix to the R8-validated kernel (single-buffered smem,
// synchronous loads, same swizzle + ldmatrix fragment mapping). Only change: operands are
// pre-split bf16 in gmem, so the load phase is straight LDG.128 -> STS.128 (no fp32, no convert).

#define LDM_X4(R, addr) \
    asm volatile("ldmatrix.sync.aligned.m8n8.x4.shared.b16 {%0,%1,%2,%3}, [%4];" \
                 : "=r"((R)[0]), "=r"((R)[1]), "=r"((R)[2]), "=r"((R)[3]) : "r"(addr))

#define MMA16816(D, Aa, Bb) \
    asm volatile("mma.sync.aligned.m16n8k16.row.col.f32.bf16.bf16.f32 " \
                 "{%0,%1,%2,%3}, {%4,%5,%6,%7}, {%8,%9}, {%0,%1,%2,%3};" \
                 : "+f"((D)[0]), "+f"((D)[1]), "+f"((D)[2]), "+f"((D)[3]) \
                 : "r"((Aa)[0]), "r"((Aa)[1]), "r"((Aa)[2]), "r"((Aa)[3]), \
                   "r"((Bb)[0]), "r"((Bb)[1]))

__global__ __launch_bounds__(256) void gemm_bf16_split2(
    const __nv_bfloat16* __restrict__ Ahi, const __nv_bfloat16* __restrict__ Alo,
    const __nv_bfloat16* __restrict__ Whi, const __nv_bfloat16* __restrict__ Wlo,
    const float* __restrict__ bias, float* __restrict__ C)
{
    extern __shared__ unsigned char smem[];
    const unsigned oAhi = 0, oAlo = 16384, oWhi = 32768, oWlo = 49152;
    unsigned sbase = (unsigned)__cvta_generic_to_shared(smem);

    int tid = threadIdx.x;
    int m0 = blockIdx.x * 128;
    int n0 = blockIdx.y * 128;
    int warp = tid >> 5, lane = tid & 31;
    int wm = (warp & 1) * 64;        // warp M offset within tile
    int wn = (warp >> 1) * 32;       // warp N offset within tile

    float acc[4][4][4];
#pragma unroll
    for (int i = 0; i < 4; i++)
#pragma unroll
        for (int j = 0; j < 4; j++)
#pragma unroll
            for (int k = 0; k < 4; k++) acc[i][j][k] = 0.f;

    for (int k0 = 0; k0 < 512; k0 += 64) {
        // ---- load all four bf16 tiles (16B vectors, swizzled) ----
#pragma unroll
        for (int i = 0; i < 4; i++) {
            int id = tid + i * 256;            // 0..1023  (128 rows x 8 chunks)
            int r = id >> 3, c = id & 7;
            unsigned dst = (unsigned)(r * 128 + ((c ^ (r & 7)) << 4));
            *reinterpret_cast<uint4*>(smem + oAhi + dst) =
                *reinterpret_cast<const uint4*>(Ahi + (size_t)(m0 + r) * 512 + k0 + c * 8);
            *reinterpret_cast<uint4*>(smem + oAlo + dst) =
                *reinterpret_cast<const uint4*>(Alo + (size_t)(m0 + r) * 512 + k0 + c * 8);
            *reinterpret_cast<uint4*>(smem + oWhi + dst) =
                *reinterpret_cast<const uint4*>(Whi + (size_t)(n0 + r) * 512 + k0 + c * 8);
            *reinterpret_cast<uint4*>(smem + oWlo + dst) =
                *reinterpret_cast<const uint4*>(Wlo + (size_t)(n0 + r) * 512 + k0 + c * 8);
        }
        __syncthreads();

        // ---- compute: 4 k16 steps per chunk ----
#pragma unroll
        for (int kk = 0; kk < 64; kk += 16) {
            unsigned a_hi[4][4], a_lo[4][4];
#pragma unroll
            for (int ma = 0; ma < 4; ma++) {
                int r = wm + ma * 16 + (lane & 15);
                int c = (kk >> 3) + (lane >> 4);
                unsigned off = (unsigned)(r * 128 + ((c ^ (r & 7)) << 4));
                LDM_X4(a_hi[ma], sbase + oAhi + off);
                LDM_X4(a_lo[ma], sbase + oAlo + off);
            }
#pragma unroll
            for (int nb = 0; nb < 2; nb++) {
                int g  = lane >> 3;
                int rn = wn + nb * 16 + ((g >> 1) << 3) + (lane & 7);
                int c  = (kk >> 3) + (g & 1);
                unsigned off = (unsigned)(rn * 128 + ((c ^ (rn & 7)) << 4));
                unsigned b_hi[4], b_lo[4];
                LDM_X4(b_hi, sbase + oWhi + off);
                LDM_X4(b_lo, sbase + oWlo + off);
#pragma unroll
                for (int ma = 0; ma < 4; ma++) {
#pragma unroll
                    for (int s = 0; s < 2; s++) {
                        int na = nb * 2 + s;
                        MMA16816(acc[ma][na], a_hi[ma], b_hi + s * 2);
                        MMA16816(acc[ma][na], a_hi[ma], b_lo + s * 2);
                        MMA16816(acc[ma][na], a_lo[ma], b_hi + s * 2);
                    }
                }
            }
        }
        __syncthreads();
    }

    // ---- epilogue: add bias, store fp32 ----
#pragma unroll
    for (int ma = 0; ma < 4; ma++) {
        int mrow = m0 + wm + ma * 16 + (lane >> 2);
#pragma unroll
        for (int na = 0; na < 4; na++) {
            int nc = n0 + wn + na * 8 + (lane & 3) * 2;
            float b0 = bias[nc], b1 = bias[nc + 1];
            float2 v0 = {acc[ma][na][0] + b0, acc[ma][na][1] + b1};
            float2 v1 = {acc[ma][na][2] + b0, acc[ma][na][3] + b1};
            *reinterpret_cast<float2*>(C + (size_t)mrow * V + nc)       = v0;
            *reinterpret_cast<float2*>(C + (size_t)(mrow + 8) * V + nc) = v1;
        }
    }
}

// ---------------- launcher ----------------
extern "C" void kernel_launch(void* const* d_in, const int* in_sizes, int n_in,
                              void* d_out, int out_size) {
    const int*   targets = (const int*)  d_in[0];
    const float* ench    = (const float*)d_in[1];
    const float* hn      = (const float*)d_in[2];
    const float* cn      = (const float*)d_in[3];
    int off = (in_sizes[4] == 1) ? 5 : 4;
    const float* emb  = (const float*)d_in[off + 0];
    const float* lng  = (const float*)d_in[off + 1];
    const float* lnb  = (const float*)d_in[off + 2];
    const float* leg  = (const float*)d_in[off + 3];
    const float* leb  = (const float*)d_in[off + 4];
    const float* phw  = (const float*)d_in[off + 5];
    const float* phb  = (const float*)d_in[off + 6];
    const float* pcw  = (const float*)d_in[off + 7];
    const float* pcb  = (const float*)d_in[off + 8];
    const float* qw   = (const float*)d_in[off + 9];
    const float* qb   = (const float*)d_in[off + 10];
    const float* kw   = (const float*)d_in[off + 11];
    const float* ew   = (const float*)d_in[off + 12];
    const float* wih  = (const float*)d_in[off + 13];
    const float* whh  = (const float*)d_in[off + 14];
    const float* bih  = (const float*)d_in[off + 15];
    const float* bhh  = (const float*)d_in[off + 16];
    const float* outw = (const float*)d_in[off + 17];
    const float* outb = (const float*)d_in[off + 18];

    float *p_enc, *p_pk, *p_x, *p_gx, *p_hs;
    __nv_bfloat16 *p_whi, *p_wlo, *p_ahi, *p_alo;
    cudaGetSymbolAddress((void**)&p_enc, g_enc);
    cudaGetSymbolAddress((void**)&p_pk,  g_pk);
    cudaGetSymbolAddress((void**)&p_x,   g_x);
    cudaGetSymbolAddress((void**)&p_gx,  g_gx);
    cudaGetSymbolAddress((void**)&p_hs,  g_hs);
    cudaGetSymbolAddress((void**)&p_whi, g_whi);
    cudaGetSymbolAddress((void**)&p_wlo, g_wlo);
    cudaGetSymbolAddress((void**)&p_ahi, g_ahi);
    cudaGetSymbolAddress((void**)&p_alo, g_alo);

    cudaFuncSetAttribute(gemm_bf16_split2,
                         cudaFuncAttributeMaxDynamicSharedMemorySize, 65536);

    // prologue (convert_w is independent; done up front)
    split_bf16_kernel<<<(V * H) / 1024, 256>>>(outw, p_whi, p_wlo);
    init_hc_kernel<<<B, 512>>>(hn, cn, phw, phb, pcw, pcb);
    ln512_kernel<<<B * S, 256>>>(ench, lng, lnb, p_enc);
    emb_ln_kernel<<<B * T, 256>>>(targets, emb, leg, leb);
    // pk = enc @ k_w^T   [4096,512] x [512,512]
    gemm64<<<dim3(64, 8), 256>>>(p_enc, 512, kw, 512, nullptr, p_pk, 512, 512);
    // gx = x_all @ w_ih[:,512:768]^T  [2048,256]
    gemm64<<<dim3(32, 32), 256>>>(p_x, 256, wih + 512, 768, nullptr, p_gx, 2048, 256);

    // sequential decode loop (graph-replayed launches — cheaper than SW grid barriers, per R9)
    for (int t = 0; t < T; t++) {
        attn_kernel<<<B, 256>>>(qw, qb, ew);
        gates_part_kernel<<<dim3(32, 4), 256>>>(wih, whh);
        lstm_kernel<<<B, 512>>>(bih, bhh, t);
    }

    // convert hs to bf16 hi/lo, then tensor-core projection
    split_bf16_kernel<<<(B * T * H) / 1024, 256>>>(p_hs, p_ahi, p_alo);
    gemm_bf16_split2<<<dim3(16, 250), 256, 65536>>>(
        p_ahi, p_alo, p_whi, p_wlo, outb, (float*)d_out);
}